// round 2
// baseline (speedup 1.0000x reference)
#include <cuda_runtime.h>
#include <cuda_bf16.h>
#include <math_constants.h>

// Problem constants (fixed by the dataset)
#define NN 50000
#define EE 1600000
#define IN_SIZE 128
#define HD 128        // NUM_HEADS * OUT_SIZE = 4*32
#define NHEADS 4
#define DOUT 32

// Scratch (device globals — no allocation allowed)
__device__ float g_h[(size_t)NN * HD];       // projected features [N, H*D]
__device__ int   g_rowstart[NN + 1];         // CSR row pointer from sorted dst

// ---------------------------------------------------------------------------
// Kernel 1: h = feat @ W   (one row per block, 128 threads = 128 output cols)
// feat row broadcast from shared; W column-slab stays hot in L1 (64 KB).
// ---------------------------------------------------------------------------
__global__ void __launch_bounds__(128) proj_gemm_kernel(
    const float* __restrict__ feat, const float* __restrict__ W)
{
    __shared__ float fs[IN_SIZE];
    const int n = blockIdx.x;
    const int t = threadIdx.x;

    fs[t] = feat[(size_t)n * IN_SIZE + t];
    __syncthreads();

    float acc = 0.f;
#pragma unroll 16
    for (int k = 0; k < IN_SIZE; k++) {
        acc = fmaf(fs[k], __ldg(&W[k * HD + t]), acc);
    }
    g_h[(size_t)n * HD + t] = acc;
}

// ---------------------------------------------------------------------------
// Kernel 2: row pointer via binary search in sorted dst
// ---------------------------------------------------------------------------
__global__ void rowptr_kernel(const int* __restrict__ dst, int E, int N)
{
    int v = blockIdx.x * blockDim.x + threadIdx.x;
    if (v > N) return;
    int lo = 0, hi = E;
    while (lo < hi) {
        int mid = (lo + hi) >> 1;
        if (dst[mid] < v) lo = mid + 1; else hi = mid;
    }
    g_rowstart[v] = lo;
}

// ---------------------------------------------------------------------------
// Kernel 3: fused edge-score + edge-softmax + aggregation.
// One block per destination node. Thread t = head*32 + d.
// Warp w == head w -> per-head dot product is an intra-warp reduction.
// Online softmax: each h[src] row gathered exactly once.
// ---------------------------------------------------------------------------
__global__ void __launch_bounds__(128) edge_fused_kernel(
    const int* __restrict__ src, float* __restrict__ out)
{
    const int v = blockIdx.x;
    const int t = threadIdx.x;

    const int start = g_rowstart[v];
    const int end   = g_rowstart[v + 1];

    if (start >= end) {               // no incoming edges -> zero output
        out[(size_t)v * HD + t] = 0.f;
        return;
    }

    const float hv = g_h[(size_t)v * HD + t];
    const float scale = 0.17677669529663689f;   // 1/sqrt(32)

    float m = -CUDART_INF_F;
    float s = 0.f;
    float acc = 0.f;

    // 1-deep prefetch of next edge's gathered row (hide L2 latency)
    float hs_next = g_h[(size_t)src[start] * HD + t];

    for (int i = start; i < end; i++) {
        const float hs = hs_next;
        if (i + 1 < end) {
            hs_next = g_h[(size_t)src[i + 1] * HD + t];
        }

        // per-head dot product: reduce over 32 lanes of this warp (= one head)
        float p = hs * hv;
#pragma unroll
        for (int o = 16; o > 0; o >>= 1)
            p += __shfl_xor_sync(0xffffffffu, p, o);
        const float sc = p * scale;

        // online softmax update (m starts at -inf: first r = exp(-inf) = 0)
        const float mn = fmaxf(m, sc);
        const float r  = __expf(m - mn);
        s   = s * r;
        acc = acc * r;
        m   = mn;
        const float w = __expf(sc - mn);
        s   += w;
        acc = fmaf(w, hs, acc);
    }

    out[(size_t)v * HD + t] = acc / s;
}

// ---------------------------------------------------------------------------
// Launch: inputs are feat[f32 N*128], src[i32 E], dst[i32 E], W[f32 128*128]
// ---------------------------------------------------------------------------
extern "C" void kernel_launch(void* const* d_in, const int* in_sizes, int n_in,
                              void* d_out, int out_size)
{
    const float* feat = (const float*)d_in[0];
    const int*   src  = (const int*)d_in[1];
    const int*   dst  = (const int*)d_in[2];
    const float* W    = (const float*)d_in[3];
    float*       out  = (float*)d_out;

    const int N = in_sizes[0] / IN_SIZE;   // 50000
    const int E = in_sizes[1];             // 1600000

    proj_gemm_kernel<<<N, 128>>>(feat, W);
    rowptr_kernel<<<(N + 1 + 255) / 256, 256>>>(dst, E, N);
    edge_fused_kernel<<<N, 128>>>(src, out);
}

// round 4
// speedup vs baseline: 1.2416x; 1.2416x over previous
#include <cuda_runtime.h>
#include <cuda_bf16.h>
#include <math_constants.h>

#define NN 50000
#define EE 1600000
#define IN_SIZE 128
#define HD 128        // NUM_HEADS * OUT_SIZE = 4*32
#define NHEADS 4
#define DOUT 32
#define NPB 20        // nodes per block in GEMM (50000/20 = 2500 blocks exactly)
#define CH 64         // edges per chunk in edge kernel

// Scratch (device globals — no allocation allowed)
__device__ float g_h[(size_t)NN * HD];       // projected features [N, H*D]
__device__ float g_Wt[HD * IN_SIZE];         // W transposed: Wt[col][k]
__device__ int   g_rowstart[NN + 1];         // CSR row pointer from sorted dst

// ---------------------------------------------------------------------------
// Kernel 0: transpose W (64KB, trivial)
// ---------------------------------------------------------------------------
__global__ void transpose_w_kernel(const float* __restrict__ W)
{
    // Wt[col][k] = W[k][col]
    g_Wt[blockIdx.x * IN_SIZE + threadIdx.x] = W[threadIdx.x * HD + blockIdx.x];
}

// ---------------------------------------------------------------------------
// Kernel 1: h = feat @ W  — 20 nodes/block, 128 threads (thread = out col).
// W-column contiguous via g_Wt -> LDG.128, amortized over 20 nodes.
// ---------------------------------------------------------------------------
__global__ void __launch_bounds__(128) proj_gemm_kernel(
    const float* __restrict__ feat)
{
    __shared__ float fs[NPB][IN_SIZE];
    const int n0 = blockIdx.x * NPB;
    const int t  = threadIdx.x;

#pragma unroll
    for (int n = 0; n < NPB; n++)
        fs[n][t] = feat[(size_t)(n0 + n) * IN_SIZE + t];
    __syncthreads();

    float acc[NPB];
#pragma unroll
    for (int n = 0; n < NPB; n++) acc[n] = 0.f;

    const float4* wt = (const float4*)&g_Wt[t * IN_SIZE];

#pragma unroll 4
    for (int k4 = 0; k4 < IN_SIZE / 4; k4++) {
        const float4 wv = __ldg(&wt[k4]);
#pragma unroll
        for (int n = 0; n < NPB; n++) {
            const float4 f = *(const float4*)&fs[n][k4 * 4];
            acc[n] = fmaf(f.x, wv.x, acc[n]);
            acc[n] = fmaf(f.y, wv.y, acc[n]);
            acc[n] = fmaf(f.z, wv.z, acc[n]);
            acc[n] = fmaf(f.w, wv.w, acc[n]);
        }
    }

#pragma unroll
    for (int n = 0; n < NPB; n++)
        g_h[(size_t)(n0 + n) * HD + t] = acc[n];
}

// ---------------------------------------------------------------------------
// Kernel 2: row pointer via binary search in sorted dst
// ---------------------------------------------------------------------------
__global__ void rowptr_kernel(const int* __restrict__ dst, int E, int N)
{
    int v = blockIdx.x * blockDim.x + threadIdx.x;
    if (v > N) return;
    int lo = 0, hi = E;
    while (lo < hi) {
        int mid = (lo + hi) >> 1;
        if (dst[mid] < v) lo = mid + 1; else hi = mid;
    }
    g_rowstart[v] = lo;
}

// ---------------------------------------------------------------------------
// Kernel 3: fused edge-score + edge-softmax + aggregation.
// One block per dst node. 64-edge chunks staged in shared; score phase:
// warp-per-edge (1 LDG.128/lane covers the row); softmax once per chunk;
// aggregation from shared (conflict-free, weights via float4 broadcast).
// ---------------------------------------------------------------------------
__global__ void __launch_bounds__(128) edge_fused_kernel(
    const int* __restrict__ src, float* __restrict__ out)
{
    __shared__ float sh_hs[CH][132];      // padded: conflict-free col reads
    __shared__ float sh_sc[NHEADS][CH];
    __shared__ float sh_w[NHEADS][CH];
    __shared__ int   sh_src[CH];
    __shared__ float sh_r[NHEADS];

    const int v = blockIdx.x;
    const int t = threadIdx.x;
    const int w = t >> 5;     // warp == head (for softmax/agg roles)
    const int l = t & 31;

    const int start = g_rowstart[v];
    const int end   = g_rowstart[v + 1];

    if (start >= end) {
        out[(size_t)v * HD + t] = 0.f;
        return;
    }

    // per-lane slice of destination row (cols 4l..4l+3), used by score role
    const float4 hv4 = *(const float4*)&g_h[(size_t)v * HD + 4 * l];
    const float scale = 0.17677669529663689f;   // 1/sqrt(32)

    float m = -CUDART_INF_F;
    float s = 0.f;
    float acc = 0.f;

    for (int base = start; base < end; base += CH) {
        const int n = min(CH, end - base);

        if (t < n) sh_src[t] = src[base + t];
        __syncthreads();

        // ---- score phase: warp handles edges e = w, w+4, ... (prefetched)
        {
            int e = w;
            float4 hs4;
            if (e < n)
                hs4 = *(const float4*)&g_h[(size_t)sh_src[e] * HD + 4 * l];
            while (e < n) {
                const int en = e + 4;
                const float4 cur = hs4;
                if (en < n)
                    hs4 = *(const float4*)&g_h[(size_t)sh_src[en] * HD + 4 * l];

                *(float4*)&sh_hs[e][4 * l] = cur;

                float p = cur.x * hv4.x;
                p = fmaf(cur.y, hv4.y, p);
                p = fmaf(cur.z, hv4.z, p);
                p = fmaf(cur.w, hv4.w, p);
                // reduce within 8-lane groups (one head per group)
                p += __shfl_xor_sync(0xffffffffu, p, 1);
                p += __shfl_xor_sync(0xffffffffu, p, 2);
                p += __shfl_xor_sync(0xffffffffu, p, 4);
                if ((l & 7) == 0) sh_sc[l >> 3][e] = p * scale;

                e = en;
            }
        }
        __syncthreads();

        // ---- chunk softmax: warp w owns head w
        float sc1 = (l      < n) ? sh_sc[w][l]      : -CUDART_INF_F;
        float sc2 = (l + 32 < n) ? sh_sc[w][l + 32] : -CUDART_INF_F;
        float cm = fmaxf(sc1, sc2);
#pragma unroll
        for (int o = 16; o > 0; o >>= 1)
            cm = fmaxf(cm, __shfl_xor_sync(0xffffffffu, cm, o));

        const float nm = fmaxf(m, cm);
        const float r  = __expf(m - nm);
        const float w1 = (l      < n) ? __expf(sc1 - nm) : 0.f;
        const float w2 = (l + 32 < n) ? __expf(sc2 - nm) : 0.f;
        sh_w[w][l]      = w1;
        sh_w[w][l + 32] = w2;

        float ws = w1 + w2;
#pragma unroll
        for (int o = 16; o > 0; o >>= 1)
            ws += __shfl_xor_sync(0xffffffffu, ws, o);
        s = s * r + ws;
        m = nm;
        if (l == 0) sh_r[w] = r;
        __syncthreads();

        // ---- aggregation: thread t accumulates column t
        acc *= sh_r[w];
        const int n4 = n & ~3;
        for (int e0 = 0; e0 < n4; e0 += 4) {
            const float4 wt4 = *(const float4*)&sh_w[w][e0];
            acc = fmaf(wt4.x, sh_hs[e0    ][t], acc);
            acc = fmaf(wt4.y, sh_hs[e0 + 1][t], acc);
            acc = fmaf(wt4.z, sh_hs[e0 + 2][t], acc);
            acc = fmaf(wt4.w, sh_hs[e0 + 3][t], acc);
        }
        for (int e = n4; e < n; e++)
            acc = fmaf(sh_w[w][e], sh_hs[e][t], acc);
        __syncthreads();   // protect sh_hs/sh_src before next chunk
    }

    out[(size_t)v * HD + t] = acc / s;
}

// ---------------------------------------------------------------------------
// Launch
// ---------------------------------------------------------------------------
extern "C" void kernel_launch(void* const* d_in, const int* in_sizes, int n_in,
                              void* d_out, int out_size)
{
    const float* feat = (const float*)d_in[0];
    const int*   src  = (const int*)d_in[1];
    const int*   dst  = (const int*)d_in[2];
    const float* W    = (const float*)d_in[3];
    float*       out  = (float*)d_out;

    const int N = in_sizes[0] / IN_SIZE;   // 50000
    const int E = in_sizes[1];             // 1600000

    transpose_w_kernel<<<HD, IN_SIZE>>>(W);
    proj_gemm_kernel<<<N / NPB, 128>>>(feat);
    rowptr_kernel<<<(N + 1 + 255) / 256, 256>>>(dst, E, N);
    edge_fused_kernel<<<N, 128>>>(src, out);
}

// round 6
// speedup vs baseline: 2.2334x; 1.7989x over previous
#include <cuda_runtime.h>
#include <cuda_bf16.h>
#include <math_constants.h>

#define NN 50000
#define EE 1600000
#define IN_SIZE 128
#define HD 128        // NUM_HEADS * OUT_SIZE = 4*32
#define NHEADS 4
#define DOUT 32
#define NPB 25        // nodes per block in GEMM (50000/25 = 2000 blocks)
#define WPB 8         // warps (nodes) per block in edge kernel

// Scratch (device globals — no allocation allowed)
__device__ float g_h[(size_t)NN * HD];       // projected features [N, H*D]
__device__ float g_Wt[HD * IN_SIZE];         // W transposed: Wt[col][k]
__device__ int   g_rowstart[NN + 1];         // CSR row pointer from sorted dst

// ---------------------------------------------------------------------------
// Kernel 0: transpose W (64KB, trivial)
// ---------------------------------------------------------------------------
__global__ void transpose_w_kernel(const float* __restrict__ W)
{
    g_Wt[blockIdx.x * IN_SIZE + threadIdx.x] = W[threadIdx.x * HD + blockIdx.x];
}

// ---------------------------------------------------------------------------
// Kernel 1: h = feat @ W  — 25 nodes/block, 128 threads (thread = out col).
// W-column contiguous via g_Wt -> one LDG.128 amortized over 100 FMAs.
// feat rows broadcast from shared (conflict-free broadcast LDS).
// ---------------------------------------------------------------------------
__global__ void __launch_bounds__(128) proj_gemm_kernel(
    const float* __restrict__ feat)
{
    __shared__ float fs[NPB][IN_SIZE];
    const int n0 = blockIdx.x * NPB;
    const int t  = threadIdx.x;

#pragma unroll
    for (int n = 0; n < NPB; n++)
        fs[n][t] = feat[(size_t)(n0 + n) * IN_SIZE + t];
    __syncthreads();

    float acc[NPB];
#pragma unroll
    for (int n = 0; n < NPB; n++) acc[n] = 0.f;

    const float4* wt = (const float4*)&g_Wt[t * IN_SIZE];

#pragma unroll 4
    for (int k4 = 0; k4 < IN_SIZE / 4; k4++) {
        const float4 wv = __ldg(&wt[k4]);
#pragma unroll
        for (int n = 0; n < NPB; n++) {
            const float4 f = *(const float4*)&fs[n][k4 * 4];
            acc[n] = fmaf(f.x, wv.x, acc[n]);
            acc[n] = fmaf(f.y, wv.y, acc[n]);
            acc[n] = fmaf(f.z, wv.z, acc[n]);
            acc[n] = fmaf(f.w, wv.w, acc[n]);
        }
    }

#pragma unroll
    for (int n = 0; n < NPB; n++)
        g_h[(size_t)(n0 + n) * HD + t] = acc[n];
}

// ---------------------------------------------------------------------------
// Kernel 2: row pointer via binary search in sorted dst
// ---------------------------------------------------------------------------
__global__ void rowptr_kernel(const int* __restrict__ dst, int E, int N)
{
    int v = blockIdx.x * blockDim.x + threadIdx.x;
    if (v > N) return;
    int lo = 0, hi = E;
    while (lo < hi) {
        int mid = (lo + hi) >> 1;
        if (dst[mid] < v) lo = mid + 1; else hi = mid;
    }
    g_rowstart[v] = lo;
}

// ---------------------------------------------------------------------------
// Kernel 3: fused edge phase — ONE WARP PER DST NODE, no smem, no barriers.
// Lane l owns cols 4l..4l+3 (all in head l>>3). Per edge: 1 LDG.128,
// dot4 + 3-shfl segmented reduce, plain exp (softmax shift-invariance:
// scores are O(1), no overflow possible), weighted accumulate in registers.
// 2-edge interleave for ILP against L2 latency.
// ---------------------------------------------------------------------------
__global__ void __launch_bounds__(WPB * 32) edge_warp_kernel(
    const int* __restrict__ src, float* __restrict__ out, int N)
{
    const int wid = threadIdx.x >> 5;
    const int l   = threadIdx.x & 31;
    const int v   = blockIdx.x * WPB + wid;
    if (v >= N) return;

    const int start = g_rowstart[v];
    const int end   = g_rowstart[v + 1];

    float4* outp = (float4*)&out[(size_t)v * HD + 4 * l];

    if (start >= end) {
        *outp = make_float4(0.f, 0.f, 0.f, 0.f);
        return;
    }

    const float4 hv = *(const float4*)&g_h[(size_t)v * HD + 4 * l];
    // log2(e) / sqrt(32): fold exp into exp2 (MUFU.EX2)
    const float C = 1.4426950408889634f * 0.17677669529663689f;

    float  s   = 0.f;
    float4 acc = make_float4(0.f, 0.f, 0.f, 0.f);

    int i = start;
    for (; i + 2 <= end; i += 2) {
        const int s0 = __ldg(&src[i]);
        const int s1 = __ldg(&src[i + 1]);
        const float4 a = *(const float4*)&g_h[(size_t)s0 * HD + 4 * l];
        const float4 b = *(const float4*)&g_h[(size_t)s1 * HD + 4 * l];

        float pa = a.x * hv.x;
        float pb = b.x * hv.x;
        pa = fmaf(a.y, hv.y, pa);  pb = fmaf(b.y, hv.y, pb);
        pa = fmaf(a.z, hv.z, pa);  pb = fmaf(b.z, hv.z, pb);
        pa = fmaf(a.w, hv.w, pa);  pb = fmaf(b.w, hv.w, pb);

        pa += __shfl_xor_sync(0xffffffffu, pa, 1);
        pb += __shfl_xor_sync(0xffffffffu, pb, 1);
        pa += __shfl_xor_sync(0xffffffffu, pa, 2);
        pb += __shfl_xor_sync(0xffffffffu, pb, 2);
        pa += __shfl_xor_sync(0xffffffffu, pa, 4);
        pb += __shfl_xor_sync(0xffffffffu, pb, 4);

        const float wa = exp2f(pa * C);
        const float wb = exp2f(pb * C);
        s += wa + wb;

        acc.x = fmaf(wa, a.x, acc.x);
        acc.y = fmaf(wa, a.y, acc.y);
        acc.z = fmaf(wa, a.z, acc.z);
        acc.w = fmaf(wa, a.w, acc.w);
        acc.x = fmaf(wb, b.x, acc.x);
        acc.y = fmaf(wb, b.y, acc.y);
        acc.z = fmaf(wb, b.z, acc.z);
        acc.w = fmaf(wb, b.w, acc.w);
    }
    if (i < end) {
        const int s0 = __ldg(&src[i]);
        const float4 a = *(const float4*)&g_h[(size_t)s0 * HD + 4 * l];
        float p = a.x * hv.x;
        p = fmaf(a.y, hv.y, p);
        p = fmaf(a.z, hv.z, p);
        p = fmaf(a.w, hv.w, p);
        p += __shfl_xor_sync(0xffffffffu, p, 1);
        p += __shfl_xor_sync(0xffffffffu, p, 2);
        p += __shfl_xor_sync(0xffffffffu, p, 4);
        const float wa = exp2f(p * C);
        s += wa;
        acc.x = fmaf(wa, a.x, acc.x);
        acc.y = fmaf(wa, a.y, acc.y);
        acc.z = fmaf(wa, a.z, acc.z);
        acc.w = fmaf(wa, a.w, acc.w);
    }

    const float inv = 1.f / s;
    *outp = make_float4(acc.x * inv, acc.y * inv, acc.z * inv, acc.w * inv);
}

// ---------------------------------------------------------------------------
// Launch
// ---------------------------------------------------------------------------
extern "C" void kernel_launch(void* const* d_in, const int* in_sizes, int n_in,
                              void* d_out, int out_size)
{
    const float* feat = (const float*)d_in[0];
    const int*   src  = (const int*)d_in[1];
    const int*   dst  = (const int*)d_in[2];
    const float* W    = (const float*)d_in[3];
    float*       out  = (float*)d_out;

    const int N = in_sizes[0] / IN_SIZE;   // 50000
    const int E = in_sizes[1];             // 1600000

    transpose_w_kernel<<<HD, IN_SIZE>>>(W);
    proj_gemm_kernel<<<N / NPB, 128>>>(feat);
    rowptr_kernel<<<(N + 1 + 255) / 256, 256>>>(dst, E, N);
    edge_warp_kernel<<<(N + WPB - 1) / WPB, WPB * 32>>>(src, out, N);
}

// round 7
// speedup vs baseline: 3.4327x; 1.5370x over previous
#include <cuda_runtime.h>
#include <cuda_bf16.h>
#include <math_constants.h>

#define NN 50000
#define IN_SIZE 128
#define HD 128        // NUM_HEADS * OUT_SIZE = 4*32
#define WPB 8         // warps (nodes) per block in edge kernel
#define TPAD 132      // smem row pad (floats): conflict-free + 16B aligned

// Scratch (device globals — no allocation allowed)
__device__ float g_h[(size_t)NN * HD];       // projected features [N, H*D]
__device__ int   g_rowstart[NN + 1];         // CSR row pointer from sorted dst

// ---------------------------------------------------------------------------
// packed fp32x2 helpers (sm_103a FFMA2 path — only reachable via PTX)
// ---------------------------------------------------------------------------
__device__ __forceinline__ void ffma2(unsigned long long& d,
                                      unsigned long long a,
                                      unsigned long long b)
{
    asm("fma.rn.f32x2 %0, %1, %2, %0;" : "+l"(d) : "l"(a), "l"(b));
}
__device__ __forceinline__ unsigned long long pack_dup(float x)
{
    unsigned long long r;
    asm("mov.b64 %0, {%1, %1};" : "=l"(r) : "f"(x));
    return r;
}
__device__ __forceinline__ float2 unpack2(unsigned long long v)
{
    float2 f;
    asm("mov.b64 {%0, %1}, %2;" : "=f"(f.x), "=f"(f.y) : "l"(v));
    return f;
}

// ---------------------------------------------------------------------------
// Kernel 1: h = feat @ W — 128x128 tile / block, 256 threads, 8x8 per thread,
// FFMA2 packed math, double-buffered 16-k smem stages.
// W is row-major [k][col] which is already the k-major layout we need.
// ---------------------------------------------------------------------------
__global__ void __launch_bounds__(256) proj_gemm_kernel(
    const float* __restrict__ feat, const float* __restrict__ W, int N)
{
    __shared__ float As[2][16][TPAD];   // [kk][row]
    __shared__ float Bs[2][16][TPAD];   // [kk][col]

    const int t  = threadIdx.x;
    const int tx = t & 15;              // col group (cols tx*4.., 64+tx*4..)
    const int ty = t >> 4;              // row group (rows ty*4.., 64+ty*4..)
    const int r0 = blockIdx.x * 128;

    // global-load roles
    const int arow = t >> 2;            // 0..63 (and +64 for second chunk)
    const int ac4  = (t & 3) * 4;       // k-offset within 16-k slice
    const int bkk  = t >> 5;            // 0..7 (and +8)
    const int bc   = (t & 31) * 4;      // col offset

    const int ra = min(r0 + arow,      N - 1);
    const int rb = min(r0 + arow + 64, N - 1);

    unsigned long long acc[8][4];
#pragma unroll
    for (int r = 0; r < 8; r++)
#pragma unroll
        for (int c = 0; c < 4; c++) acc[r][c] = 0ull;

    float4 pa0, pa1, pb0, pb1;

    // prefetch stage 0
    pa0 = *(const float4*)&feat[(size_t)ra * IN_SIZE + ac4];
    pa1 = *(const float4*)&feat[(size_t)rb * IN_SIZE + ac4];
    pb0 = *(const float4*)&W[bkk * HD + bc];
    pb1 = *(const float4*)&W[(bkk + 8) * HD + bc];

    // stage 0 -> smem
    As[0][ac4 + 0][arow] = pa0.x;  As[0][ac4 + 1][arow] = pa0.y;
    As[0][ac4 + 2][arow] = pa0.z;  As[0][ac4 + 3][arow] = pa0.w;
    As[0][ac4 + 0][arow + 64] = pa1.x;  As[0][ac4 + 1][arow + 64] = pa1.y;
    As[0][ac4 + 2][arow + 64] = pa1.z;  As[0][ac4 + 3][arow + 64] = pa1.w;
    *(float4*)&Bs[0][bkk][bc]     = pb0;
    *(float4*)&Bs[0][bkk + 8][bc] = pb1;
    __syncthreads();

#pragma unroll
    for (int s = 0; s < 8; s++) {
        const int buf = s & 1;

        if (s < 7) {   // prefetch next stage into registers
            const int k0 = (s + 1) * 16;
            pa0 = *(const float4*)&feat[(size_t)ra * IN_SIZE + k0 + ac4];
            pa1 = *(const float4*)&feat[(size_t)rb * IN_SIZE + k0 + ac4];
            pb0 = *(const float4*)&W[(k0 + bkk) * HD + bc];
            pb1 = *(const float4*)&W[(k0 + bkk + 8) * HD + bc];
        }

#pragma unroll
        for (int kk = 0; kk < 16; kk++) {
            const float4 a0 = *(const float4*)&As[buf][kk][ty * 4];
            const float4 a1 = *(const float4*)&As[buf][kk][64 + ty * 4];
            const ulonglong2 bb0 = *(const ulonglong2*)&Bs[buf][kk][tx * 4];
            const ulonglong2 bb1 = *(const ulonglong2*)&Bs[buf][kk][64 + tx * 4];
            const unsigned long long b2[4] = { bb0.x, bb0.y, bb1.x, bb1.y };
            const float ar[8] = { a0.x, a0.y, a0.z, a0.w,
                                  a1.x, a1.y, a1.z, a1.w };
#pragma unroll
            for (int r = 0; r < 8; r++) {
                const unsigned long long a2 = pack_dup(ar[r]);
                ffma2(acc[r][0], a2, b2[0]);
                ffma2(acc[r][1], a2, b2[1]);
                ffma2(acc[r][2], a2, b2[2]);
                ffma2(acc[r][3], a2, b2[3]);
            }
        }

        if (s < 7) {
            const int nb = buf ^ 1;
            As[nb][ac4 + 0][arow] = pa0.x;  As[nb][ac4 + 1][arow] = pa0.y;
            As[nb][ac4 + 2][arow] = pa0.z;  As[nb][ac4 + 3][arow] = pa0.w;
            As[nb][ac4 + 0][arow + 64] = pa1.x;  As[nb][ac4 + 1][arow + 64] = pa1.y;
            As[nb][ac4 + 2][arow + 64] = pa1.z;  As[nb][ac4 + 3][arow + 64] = pa1.w;
            *(float4*)&Bs[nb][bkk][bc]     = pb0;
            *(float4*)&Bs[nb][bkk + 8][bc] = pb1;
            __syncthreads();
        }
    }

    // epilogue: 8 rows x 2 float4 stores
#pragma unroll
    for (int rg = 0; rg < 2; rg++) {
#pragma unroll
        for (int i = 0; i < 4; i++) {
            const int row = r0 + rg * 64 + ty * 4 + i;
            if (row < N) {
                const int r = rg * 4 + i;
                const float2 u0 = unpack2(acc[r][0]);
                const float2 u1 = unpack2(acc[r][1]);
                const float2 u2 = unpack2(acc[r][2]);
                const float2 u3 = unpack2(acc[r][3]);
                *(float4*)&g_h[(size_t)row * HD + tx * 4] =
                    make_float4(u0.x, u0.y, u1.x, u1.y);
                *(float4*)&g_h[(size_t)row * HD + 64 + tx * 4] =
                    make_float4(u2.x, u2.y, u3.x, u3.y);
            }
        }
    }
}

// ---------------------------------------------------------------------------
// Kernel 2: row pointer via binary search in sorted dst
// ---------------------------------------------------------------------------
__global__ void rowptr_kernel(const int* __restrict__ dst, int E, int N)
{
    int v = blockIdx.x * blockDim.x + threadIdx.x;
    if (v > N) return;
    int lo = 0, hi = E;
    while (lo < hi) {
        int mid = (lo + hi) >> 1;
        if (dst[mid] < v) lo = mid + 1; else hi = mid;
    }
    g_rowstart[v] = lo;
}

// ---------------------------------------------------------------------------
// Kernel 3: fused edge phase — one warp per dst node, no smem/barriers.
// Split accumulators (a-slot / b-slot) halve the serial FMA chain.
// ---------------------------------------------------------------------------
__global__ void __launch_bounds__(WPB * 32) edge_warp_kernel(
    const int* __restrict__ src, float* __restrict__ out, int N)
{
    const int wid = threadIdx.x >> 5;
    const int l   = threadIdx.x & 31;
    const int v   = blockIdx.x * WPB + wid;
    if (v >= N) return;

    const int start = g_rowstart[v];
    const int end   = g_rowstart[v + 1];

    float4* outp = (float4*)&out[(size_t)v * HD + 4 * l];

    if (start >= end) {
        *outp = make_float4(0.f, 0.f, 0.f, 0.f);
        return;
    }

    const float4 hv = *(const float4*)&g_h[(size_t)v * HD + 4 * l];
    // log2(e)/sqrt(32): fold exp into exp2; scores are O(1), no overflow
    const float C = 1.4426950408889634f * 0.17677669529663689f;

    float  sA = 0.f, sB = 0.f;
    float4 accA = make_float4(0.f, 0.f, 0.f, 0.f);
    float4 accB = make_float4(0.f, 0.f, 0.f, 0.f);

    int i = start;
    for (; i + 2 <= end; i += 2) {
        const int s0 = __ldg(&src[i]);
        const int s1 = __ldg(&src[i + 1]);
        const float4 a = *(const float4*)&g_h[(size_t)s0 * HD + 4 * l];
        const float4 b = *(const float4*)&g_h[(size_t)s1 * HD + 4 * l];

        float pa = a.x * hv.x;
        float pb = b.x * hv.x;
        pa = fmaf(a.y, hv.y, pa);  pb = fmaf(b.y, hv.y, pb);
        pa = fmaf(a.z, hv.z, pa);  pb = fmaf(b.z, hv.z, pb);
        pa = fmaf(a.w, hv.w, pa);  pb = fmaf(b.w, hv.w, pb);

        pa += __shfl_xor_sync(0xffffffffu, pa, 1);
        pb += __shfl_xor_sync(0xffffffffu, pb, 1);
        pa += __shfl_xor_sync(0xffffffffu, pa, 2);
        pb += __shfl_xor_sync(0xffffffffu, pb, 2);
        pa += __shfl_xor_sync(0xffffffffu, pa, 4);
        pb += __shfl_xor_sync(0xffffffffu, pb, 4);

        const float wa = exp2f(pa * C);
        const float wb = exp2f(pb * C);
        sA += wa;
        sB += wb;

        accA.x = fmaf(wa, a.x, accA.x);  accB.x = fmaf(wb, b.x, accB.x);
        accA.y = fmaf(wa, a.y, accA.y);  accB.y = fmaf(wb, b.y, accB.y);
        accA.z = fmaf(wa, a.z, accA.z);  accB.z = fmaf(wb, b.z, accB.z);
        accA.w = fmaf(wa, a.w, accA.w);  accB.w = fmaf(wb, b.w, accB.w);
    }
    if (i < end) {
        const int s0 = __ldg(&src[i]);
        const float4 a = *(const float4*)&g_h[(size_t)s0 * HD + 4 * l];
        float p = a.x * hv.x;
        p = fmaf(a.y, hv.y, p);
        p = fmaf(a.z, hv.z, p);
        p = fmaf(a.w, hv.w, p);
        p += __shfl_xor_sync(0xffffffffu, p, 1);
        p += __shfl_xor_sync(0xffffffffu, p, 2);
        p += __shfl_xor_sync(0xffffffffu, p, 4);
        const float wa = exp2f(p * C);
        sA += wa;
        accA.x = fmaf(wa, a.x, accA.x);
        accA.y = fmaf(wa, a.y, accA.y);
        accA.z = fmaf(wa, a.z, accA.z);
        accA.w = fmaf(wa, a.w, accA.w);
    }

    const float inv = 1.f / (sA + sB);
    *outp = make_float4((accA.x + accB.x) * inv,
                        (accA.y + accB.y) * inv,
                        (accA.z + accB.z) * inv,
                        (accA.w + accB.w) * inv);
}

// ---------------------------------------------------------------------------
// Launch
// ---------------------------------------------------------------------------
extern "C" void kernel_launch(void* const* d_in, const int* in_sizes, int n_in,
                              void* d_out, int out_size)
{
    const float* feat = (const float*)d_in[0];
    const int*   src  = (const int*)d_in[1];
    const int*   dst  = (const int*)d_in[2];
    const float* W    = (const float*)d_in[3];
    float*       out  = (float*)d_out;

    const int N = in_sizes[0] / IN_SIZE;   // 50000
    const int E = in_sizes[1];             // 1600000

    rowptr_kernel<<<(N + 1 + 255) / 256, 256>>>(dst, E, N);
    proj_gemm_kernel<<<(N + 127) / 128, 256>>>(feat, W, N);
    edge_warp_kernel<<<(N + WPB - 1) / WPB, WPB * 32>>>(src, out, N);
}

// round 8
// speedup vs baseline: 3.6098x; 1.0516x over previous
#include <cuda_runtime.h>
#include <cuda_fp16.h>
#include <cuda_bf16.h>
#include <math_constants.h>

#define NN 50000
#define IN_SIZE 128
#define HD 128        // NUM_HEADS * OUT_SIZE = 4*32
#define WPB 8         // warps (nodes) per block in edge kernel
#define TPAD 132      // smem row pad (floats): conflict-free + 16B aligned

// Scratch (device globals — no allocation allowed)
__device__ __half g_hh[(size_t)NN * HD];     // projected features, fp16 [N, H*D]
__device__ int    g_rowstart[NN + 1];        // CSR row pointer from sorted dst

// ---------------------------------------------------------------------------
// packed fp32x2 helpers (sm_103a FFMA2 path — only reachable via PTX)
// ---------------------------------------------------------------------------
__device__ __forceinline__ void ffma2(unsigned long long& d,
                                      unsigned long long a,
                                      unsigned long long b)
{
    asm("fma.rn.f32x2 %0, %1, %2, %0;" : "+l"(d) : "l"(a), "l"(b));
}
__device__ __forceinline__ unsigned long long pack_dup(float x)
{
    unsigned long long r;
    asm("mov.b64 %0, {%1, %1};" : "=l"(r) : "f"(x));
    return r;
}
__device__ __forceinline__ float2 unpack2(unsigned long long v)
{
    float2 f;
    asm("mov.b64 {%0, %1}, %2;" : "=f"(f.x), "=f"(f.y) : "l"(v));
    return f;
}
// 4 halves (as uint2) -> float4
__device__ __forceinline__ float4 h4_to_f4(uint2 u)
{
    const __half2 h0 = *reinterpret_cast<const __half2*>(&u.x);
    const __half2 h1 = *reinterpret_cast<const __half2*>(&u.y);
    const float2 f0 = __half22float2(h0);
    const float2 f1 = __half22float2(h1);
    return make_float4(f0.x, f0.y, f1.x, f1.y);
}

// ---------------------------------------------------------------------------
// Kernel 1: h = feat @ W — 128x128 tile / block, 256 threads, 8x8 per thread,
// FFMA2 packed math, double-buffered 16-k smem stages. Epilogue -> fp16.
// ---------------------------------------------------------------------------
__global__ void __launch_bounds__(256) proj_gemm_kernel(
    const float* __restrict__ feat, const float* __restrict__ W, int N)
{
    __shared__ float As[2][16][TPAD];   // [kk][row]
    __shared__ float Bs[2][16][TPAD];   // [kk][col]

    const int t  = threadIdx.x;
    const int tx = t & 15;              // col group (cols tx*4.., 64+tx*4..)
    const int ty = t >> 4;              // row group (rows ty*4.., 64+ty*4..)
    const int r0 = blockIdx.x * 128;

    const int arow = t >> 2;            // 0..63 (and +64)
    const int ac4  = (t & 3) * 4;       // k-offset within 16-k slice
    const int bkk  = t >> 5;            // 0..7 (and +8)
    const int bc   = (t & 31) * 4;      // col offset

    const int ra = min(r0 + arow,      N - 1);
    const int rb = min(r0 + arow + 64, N - 1);

    unsigned long long acc[8][4];
#pragma unroll
    for (int r = 0; r < 8; r++)
#pragma unroll
        for (int c = 0; c < 4; c++) acc[r][c] = 0ull;

    float4 pa0, pa1, pb0, pb1;

    pa0 = *(const float4*)&feat[(size_t)ra * IN_SIZE + ac4];
    pa1 = *(const float4*)&feat[(size_t)rb * IN_SIZE + ac4];
    pb0 = *(const float4*)&W[bkk * HD + bc];
    pb1 = *(const float4*)&W[(bkk + 8) * HD + bc];

    As[0][ac4 + 0][arow] = pa0.x;  As[0][ac4 + 1][arow] = pa0.y;
    As[0][ac4 + 2][arow] = pa0.z;  As[0][ac4 + 3][arow] = pa0.w;
    As[0][ac4 + 0][arow + 64] = pa1.x;  As[0][ac4 + 1][arow + 64] = pa1.y;
    As[0][ac4 + 2][arow + 64] = pa1.z;  As[0][ac4 + 3][arow + 64] = pa1.w;
    *(float4*)&Bs[0][bkk][bc]     = pb0;
    *(float4*)&Bs[0][bkk + 8][bc] = pb1;
    __syncthreads();

#pragma unroll
    for (int s = 0; s < 8; s++) {
        const int buf = s & 1;

        if (s < 7) {
            const int k0 = (s + 1) * 16;
            pa0 = *(const float4*)&feat[(size_t)ra * IN_SIZE + k0 + ac4];
            pa1 = *(const float4*)&feat[(size_t)rb * IN_SIZE + k0 + ac4];
            pb0 = *(const float4*)&W[(k0 + bkk) * HD + bc];
            pb1 = *(const float4*)&W[(k0 + bkk + 8) * HD + bc];
        }

#pragma unroll
        for (int kk = 0; kk < 16; kk++) {
            const float4 a0 = *(const float4*)&As[buf][kk][ty * 4];
            const float4 a1 = *(const float4*)&As[buf][kk][64 + ty * 4];
            const ulonglong2 bb0 = *(const ulonglong2*)&Bs[buf][kk][tx * 4];
            const ulonglong2 bb1 = *(const ulonglong2*)&Bs[buf][kk][64 + tx * 4];
            const unsigned long long b2[4] = { bb0.x, bb0.y, bb1.x, bb1.y };
            const float ar[8] = { a0.x, a0.y, a0.z, a0.w,
                                  a1.x, a1.y, a1.z, a1.w };
#pragma unroll
            for (int r = 0; r < 8; r++) {
                const unsigned long long a2 = pack_dup(ar[r]);
                ffma2(acc[r][0], a2, b2[0]);
                ffma2(acc[r][1], a2, b2[1]);
                ffma2(acc[r][2], a2, b2[2]);
                ffma2(acc[r][3], a2, b2[3]);
            }
        }

        if (s < 7) {
            const int nb = buf ^ 1;
            As[nb][ac4 + 0][arow] = pa0.x;  As[nb][ac4 + 1][arow] = pa0.y;
            As[nb][ac4 + 2][arow] = pa0.z;  As[nb][ac4 + 3][arow] = pa0.w;
            As[nb][ac4 + 0][arow + 64] = pa1.x;  As[nb][ac4 + 1][arow + 64] = pa1.y;
            As[nb][ac4 + 2][arow + 64] = pa1.z;  As[nb][ac4 + 3][arow + 64] = pa1.w;
            *(float4*)&Bs[nb][bkk][bc]     = pb0;
            *(float4*)&Bs[nb][bkk + 8][bc] = pb1;
            __syncthreads();
        }
    }

    // epilogue: fp32 acc -> fp16 rows (8 halves per row chunk = uint2 store)
#pragma unroll
    for (int rg = 0; rg < 2; rg++) {
#pragma unroll
        for (int i = 0; i < 4; i++) {
            const int row = r0 + rg * 64 + ty * 4 + i;
            if (row < N) {
                const int r = rg * 4 + i;
                const float2 u0 = unpack2(acc[r][0]);
                const float2 u1 = unpack2(acc[r][1]);
                const float2 u2 = unpack2(acc[r][2]);
                const float2 u3 = unpack2(acc[r][3]);
                uint2 o0, o1;
                *reinterpret_cast<__half2*>(&o0.x) = __floats2half2_rn(u0.x, u0.y);
                *reinterpret_cast<__half2*>(&o0.y) = __floats2half2_rn(u1.x, u1.y);
                *reinterpret_cast<__half2*>(&o1.x) = __floats2half2_rn(u2.x, u2.y);
                *reinterpret_cast<__half2*>(&o1.y) = __floats2half2_rn(u3.x, u3.y);
                *(uint2*)&g_hh[(size_t)row * HD + tx * 4]      = o0;
                *(uint2*)&g_hh[(size_t)row * HD + 64 + tx * 4] = o1;
            }
        }
    }
}

// ---------------------------------------------------------------------------
// Kernel 2: row pointer by boundary scatter over sorted dst (thread-per-edge,
// coalesced reads; total scattered writes = N+1).
// ---------------------------------------------------------------------------
__global__ void rowptr_scatter_kernel(const int* __restrict__ dst, int E, int N)
{
    const int e = blockIdx.x * blockDim.x + threadIdx.x;
    if (e >= E) return;
    const int d    = dst[e];
    const int prev = (e == 0) ? -1 : dst[e - 1];
    for (int v = prev + 1; v <= d; v++)       // rowstart[v]=e for v in (prev,d]
        g_rowstart[v] = e;
    if (e == E - 1) {
        for (int v = d + 1; v <= N; v++)
            g_rowstart[v] = E;
    }
}

// ---------------------------------------------------------------------------
// Kernel 3: fused edge phase — one warp per dst node, no smem/barriers.
// fp16 gather rows (8 B/lane), fp32 math, split accumulators.
// ---------------------------------------------------------------------------
__global__ void __launch_bounds__(WPB * 32) edge_warp_kernel(
    const int* __restrict__ src, float* __restrict__ out, int N)
{
    const int wid = threadIdx.x >> 5;
    const int l   = threadIdx.x & 31;
    const int v   = blockIdx.x * WPB + wid;
    if (v >= N) return;

    const int start = g_rowstart[v];
    const int end   = g_rowstart[v + 1];

    float4* outp = (float4*)&out[(size_t)v * HD + 4 * l];

    if (start >= end) {
        *outp = make_float4(0.f, 0.f, 0.f, 0.f);
        return;
    }

    const float4 hv = h4_to_f4(*(const uint2*)&g_hh[(size_t)v * HD + 4 * l]);
    // log2(e)/sqrt(32): fold exp into exp2; scores are O(1), no overflow
    const float C = 1.4426950408889634f * 0.17677669529663689f;

    float  sA = 0.f, sB = 0.f;
    float4 accA = make_float4(0.f, 0.f, 0.f, 0.f);
    float4 accB = make_float4(0.f, 0.f, 0.f, 0.f);

    int i = start;
    for (; i + 2 <= end; i += 2) {
        const int s0 = __ldg(&src[i]);
        const int s1 = __ldg(&src[i + 1]);
        const uint2 au = *(const uint2*)&g_hh[(size_t)s0 * HD + 4 * l];
        const uint2 bu = *(const uint2*)&g_hh[(size_t)s1 * HD + 4 * l];
        const float4 a = h4_to_f4(au);
        const float4 b = h4_to_f4(bu);

        float pa = a.x * hv.x;
        float pb = b.x * hv.x;
        pa = fmaf(a.y, hv.y, pa);  pb = fmaf(b.y, hv.y, pb);
        pa = fmaf(a.z, hv.z, pa);  pb = fmaf(b.z, hv.z, pb);
        pa = fmaf(a.w, hv.w, pa);  pb = fmaf(b.w, hv.w, pb);

        pa += __shfl_xor_sync(0xffffffffu, pa, 1);
        pb += __shfl_xor_sync(0xffffffffu, pb, 1);
        pa += __shfl_xor_sync(0xffffffffu, pa, 2);
        pb += __shfl_xor_sync(0xffffffffu, pb, 2);
        pa += __shfl_xor_sync(0xffffffffu, pa, 4);
        pb += __shfl_xor_sync(0xffffffffu, pb, 4);

        const float wa = exp2f(pa * C);
        const float wb = exp2f(pb * C);
        sA += wa;
        sB += wb;

        accA.x = fmaf(wa, a.x, accA.x);  accB.x = fmaf(wb, b.x, accB.x);
        accA.y = fmaf(wa, a.y, accA.y);  accB.y = fmaf(wb, b.y, accB.y);
        accA.z = fmaf(wa, a.z, accA.z);  accB.z = fmaf(wb, b.z, accB.z);
        accA.w = fmaf(wa, a.w, accA.w);  accB.w = fmaf(wb, b.w, accB.w);
    }
    if (i < end) {
        const int s0 = __ldg(&src[i]);
        const float4 a = h4_to_f4(*(const uint2*)&g_hh[(size_t)s0 * HD + 4 * l]);
        float p = a.x * hv.x;
        p = fmaf(a.y, hv.y, p);
        p = fmaf(a.z, hv.z, p);
        p = fmaf(a.w, hv.w, p);
        p += __shfl_xor_sync(0xffffffffu, p, 1);
        p += __shfl_xor_sync(0xffffffffu, p, 2);
        p += __shfl_xor_sync(0xffffffffu, p, 4);
        const float wa = exp2f(p * C);
        sA += wa;
        accA.x = fmaf(wa, a.x, accA.x);
        accA.y = fmaf(wa, a.y, accA.y);
        accA.z = fmaf(wa, a.z, accA.z);
        accA.w = fmaf(wa, a.w, accA.w);
    }

    const float inv = 1.f / (sA + sB);
    *outp = make_float4((accA.x + accB.x) * inv,
                        (accA.y + accB.y) * inv,
                        (accA.z + accB.z) * inv,
                        (accA.w + accB.w) * inv);
}

// ---------------------------------------------------------------------------
// Launch
// ---------------------------------------------------------------------------
extern "C" void kernel_launch(void* const* d_in, const int* in_sizes, int n_in,
                              void* d_out, int out_size)
{
    const float* feat = (const float*)d_in[0];
    const int*   src  = (const int*)d_in[1];
    const int*   dst  = (const int*)d_in[2];
    const float* W    = (const float*)d_in[3];
    float*       out  = (float*)d_out;

    const int N = in_sizes[0] / IN_SIZE;   // 50000
    const int E = in_sizes[1];             // 1600000

    rowptr_scatter_kernel<<<(E + 255) / 256, 256>>>(dst, E, N);
    proj_gemm_kernel<<<(N + 127) / 128, 256>>>(feat, W, N);
    edge_warp_kernel<<<(N + WPB - 1) / WPB, WPB * 32>>>(src, out, N);
}

// round 9
// speedup vs baseline: 3.9922x; 1.1059x over previous
#include <cuda_runtime.h>
#include <cuda_fp16.h>
#include <mma.h>
#include <math_constants.h>

using namespace nvcuda;

#define NN 50000
#define IN_SIZE 128
#define HD 128        // NUM_HEADS * OUT_SIZE = 4*32
#define WPB 8         // warps (nodes) per block in edge kernel

#define AS 136        // fp16 smem row stride (mult of 8 for wmma, pad vs conflicts)
#define GEMM_SMEM ((128 * AS * 2) * 2)   // A + B tiles, fp16

// Scratch (device globals — no allocation allowed)
__device__ __half g_hh[(size_t)NN * HD];     // projected features, fp16 [N, H*D]
__device__ int    g_rowstart[NN + 1];        // CSR row pointer from sorted dst

// 4 halves (as uint2) -> float4
__device__ __forceinline__ float4 h4_to_f4(uint2 u)
{
    const __half2 h0 = *reinterpret_cast<const __half2*>(&u.x);
    const __half2 h1 = *reinterpret_cast<const __half2*>(&u.y);
    const float2 f0 = __half22float2(h0);
    const float2 f1 = __half22float2(h1);
    return make_float4(f0.x, f0.y, f1.x, f1.y);
}
__device__ __forceinline__ uint2 f4_to_h4(float4 v)
{
    uint2 o;
    *reinterpret_cast<__half2*>(&o.x) = __floats2half2_rn(v.x, v.y);
    *reinterpret_cast<__half2*>(&o.y) = __floats2half2_rn(v.z, v.w);
    return o;
}

// ---------------------------------------------------------------------------
// Kernel 1: h = feat @ W via HMMA tensor cores.
// 128x128 tile / block, 256 threads (8 warps). Full K=128 staged once in
// smem as fp16 (conversion fused into the staging load). Warp w computes a
// 32x64 output tile: warp_row = w&3, warp_col = w>>2; 2x4 wmma 16x16 frags.
// ---------------------------------------------------------------------------
__global__ void __launch_bounds__(256) proj_gemm_kernel(
    const float* __restrict__ feat, const float* __restrict__ W, int N)
{
    extern __shared__ __half smem[];
    __half* As = smem;                 // [128][AS]
    __half* Bs = smem + 128 * AS;      // [128][AS]

    const int t    = threadIdx.x;
    const int lane = t & 31;
    const int w    = t >> 5;
    const int r0   = blockIdx.x * 128;

    // ---- stage A (feat rows, fp32 -> fp16) and B (W, fp32 -> fp16)
    {
        const int row  = t >> 1;            // 0..127
        const int colb = (t & 1) * 64;      // 0 or 64
        const int ra   = min(r0 + row, N - 1);
#pragma unroll
        for (int i = 0; i < 16; i++) {
            const float4 fa = *(const float4*)&feat[(size_t)ra * IN_SIZE + colb + i * 4];
            *(uint2*)&As[row * AS + colb + i * 4] = f4_to_h4(fa);
            const float4 fb = *(const float4*)&W[row * HD + colb + i * 4];
            *(uint2*)&Bs[row * AS + colb + i * 4] = f4_to_h4(fb);
        }
    }
    __syncthreads();

    const int warp_row = (w & 3) * 32;     // output row base within tile
    const int warp_col = (w >> 2) * 64;    // output col base

    wmma::fragment<wmma::accumulator, 16, 16, 16, float> acc[2][4];
#pragma unroll
    for (int i = 0; i < 2; i++)
#pragma unroll
        for (int j = 0; j < 4; j++)
            wmma::fill_fragment(acc[i][j], 0.f);

#pragma unroll
    for (int k0 = 0; k0 < 128; k0 += 16) {
        wmma::fragment<wmma::matrix_a, 16, 16, 16, __half, wmma::row_major> af[2];
        wmma::fragment<wmma::matrix_b, 16, 16, 16, __half, wmma::row_major> bf[4];
#pragma unroll
        for (int i = 0; i < 2; i++)
            wmma::load_matrix_sync(af[i], &As[(warp_row + i * 16) * AS + k0], AS);
#pragma unroll
        for (int j = 0; j < 4; j++)
            wmma::load_matrix_sync(bf[j], &Bs[k0 * AS + warp_col + j * 16], AS);
#pragma unroll
        for (int i = 0; i < 2; i++)
#pragma unroll
            for (int j = 0; j < 4; j++)
                wmma::mma_sync(acc[i][j], af[i], bf[j], acc[i][j]);
    }

    // ---- epilogue: frags -> smem f32 (per-warp region) -> fp16 global
    __syncthreads();                        // done reading As/Bs
    float* ep = (float*)smem + w * (32 * 64);
#pragma unroll
    for (int i = 0; i < 2; i++)
#pragma unroll
        for (int j = 0; j < 4; j++)
            wmma::store_matrix_sync(&ep[i * 16 * 64 + j * 16], acc[i][j], 64,
                                    wmma::mem_row_major);
    __syncwarp();

#pragma unroll
    for (int it = 0; it < 16; it++) {
        const int idx = it * 32 + lane;     // over 32 rows x 16 float4
        const int row = idx >> 4;
        const int c4  = (idx & 15) * 4;
        const int rg  = r0 + warp_row + row;
        if (rg < N) {
            const float4 v = *(const float4*)&ep[row * 64 + c4];
            *(uint2*)&g_hh[(size_t)rg * HD + warp_col + c4] = f4_to_h4(v);
        }
    }
}

// ---------------------------------------------------------------------------
// Kernel 2: row pointer by boundary scatter, 4 edges per thread (int4 load).
// ---------------------------------------------------------------------------
__global__ void rowptr_scatter4_kernel(const int* __restrict__ dst, int E, int N)
{
    const int g  = blockIdx.x * blockDim.x + threadIdx.x;
    const int e0 = g * 4;
    if (e0 >= E) return;

    int d0, d1, d2, d3;
    if (e0 + 3 < E) {
        const int4 v = *(const int4*)&dst[e0];
        d0 = v.x; d1 = v.y; d2 = v.z; d3 = v.w;
    } else {
        d0 = dst[e0];
        d1 = (e0 + 1 < E) ? dst[e0 + 1] : d0;
        d2 = (e0 + 2 < E) ? dst[e0 + 2] : d1;
        d3 = (e0 + 3 < E) ? dst[e0 + 3] : d2;
    }
    const int prev = (e0 == 0) ? -1 : dst[e0 - 1];

    for (int v = prev + 1; v <= d0; v++) g_rowstart[v] = e0;
    for (int v = d0 + 1;   v <= d1; v++) g_rowstart[v] = e0 + 1;
    for (int v = d1 + 1;   v <= d2; v++) g_rowstart[v] = e0 + 2;
    for (int v = d2 + 1;   v <= d3; v++) g_rowstart[v] = e0 + 3;

    if (e0 + 4 >= E) {                     // last chunk: close the tail
        for (int v = d3 + 1; v <= N; v++) g_rowstart[v] = E;
    }
}

// ---------------------------------------------------------------------------
// Kernel 3: fused edge phase — one warp per dst node, no smem/barriers.
// fp16 gather rows (8 B/lane), fp32 math. 4-edge unroll (4 gathers in
// flight vs L2 latency), src indices via one int4 per 4 edges.
// ---------------------------------------------------------------------------
__global__ void __launch_bounds__(WPB * 32) edge_warp_kernel(
    const int* __restrict__ src, float* __restrict__ out, int N)
{
    const int wid = threadIdx.x >> 5;
    const int l   = threadIdx.x & 31;
    const int v   = blockIdx.x * WPB + wid;
    if (v >= N) return;

    const int start = g_rowstart[v];
    const int end   = g_rowstart[v + 1];

    float4* outp = (float4*)&out[(size_t)v * HD + 4 * l];

    if (start >= end) {
        *outp = make_float4(0.f, 0.f, 0.f, 0.f);
        return;
    }

    const float4 hv = h4_to_f4(*(const uint2*)&g_hh[(size_t)v * HD + 4 * l]);
    // log2(e)/sqrt(32): fold exp into exp2; scores are O(1), no overflow
    const float C = 1.4426950408889634f * 0.17677669529663689f;

    float  sA = 0.f, sB = 0.f;
    float4 accA = make_float4(0.f, 0.f, 0.f, 0.f);
    float4 accB = make_float4(0.f, 0.f, 0.f, 0.f);

#define EDGE_ONE(srcidx)                                                    \
    do {                                                                    \
        const float4 a = h4_to_f4(                                          \
            *(const uint2*)&g_hh[(size_t)(srcidx) * HD + 4 * l]);           \
        float p = a.x * hv.x;                                               \
        p = fmaf(a.y, hv.y, p);                                             \
        p = fmaf(a.z, hv.z, p);                                             \
        p = fmaf(a.w, hv.w, p);                                             \
        p += __shfl_xor_sync(0xffffffffu, p, 1);                            \
        p += __shfl_xor_sync(0xffffffffu, p, 2);                            \
        p += __shfl_xor_sync(0xffffffffu, p, 4);                            \
        const float wt = exp2f(p * C);                                      \
        sA += wt;                                                           \
        accA.x = fmaf(wt, a.x, accA.x);                                     \
        accA.y = fmaf(wt, a.y, accA.y);                                     \
        accA.z = fmaf(wt, a.z, accA.z);                                     \
        accA.w = fmaf(wt, a.w, accA.w);                                     \
    } while (0)

    int i = start;
    // head: scalar until 16B-aligned src index
    while (i < end && (i & 3)) { EDGE_ONE(__ldg(&src[i])); i++; }

    for (; i + 4 <= end; i += 4) {
        const int4 s4 = *(const int4*)&src[i];
        const uint2 au = *(const uint2*)&g_hh[(size_t)s4.x * HD + 4 * l];
        const uint2 bu = *(const uint2*)&g_hh[(size_t)s4.y * HD + 4 * l];
        const uint2 cu = *(const uint2*)&g_hh[(size_t)s4.z * HD + 4 * l];
        const uint2 du = *(const uint2*)&g_hh[(size_t)s4.w * HD + 4 * l];
        const float4 a = h4_to_f4(au);
        const float4 b = h4_to_f4(bu);
        const float4 c = h4_to_f4(cu);
        const float4 d = h4_to_f4(du);

        float pa = a.x * hv.x, pb = b.x * hv.x;
        float pc = c.x * hv.x, pd = d.x * hv.x;
        pa = fmaf(a.y, hv.y, pa);  pb = fmaf(b.y, hv.y, pb);
        pc = fmaf(c.y, hv.y, pc);  pd = fmaf(d.y, hv.y, pd);
        pa = fmaf(a.z, hv.z, pa);  pb = fmaf(b.z, hv.z, pb);
        pc = fmaf(c.z, hv.z, pc);  pd = fmaf(d.z, hv.z, pd);
        pa = fmaf(a.w, hv.w, pa);  pb = fmaf(b.w, hv.w, pb);
        pc = fmaf(c.w, hv.w, pc);  pd = fmaf(d.w, hv.w, pd);

        pa += __shfl_xor_sync(0xffffffffu, pa, 1);
        pb += __shfl_xor_sync(0xffffffffu, pb, 1);
        pc += __shfl_xor_sync(0xffffffffu, pc, 1);
        pd += __shfl_xor_sync(0xffffffffu, pd, 1);
        pa += __shfl_xor_sync(0xffffffffu, pa, 2);
        pb += __shfl_xor_sync(0xffffffffu, pb, 2);
        pc += __shfl_xor_sync(0xffffffffu, pc, 2);
        pd += __shfl_xor_sync(0xffffffffu, pd, 2);
        pa += __shfl_xor_sync(0xffffffffu, pa, 4);
        pb += __shfl_xor_sync(0xffffffffu, pb, 4);
        pc += __shfl_xor_sync(0xffffffffu, pc, 4);
        pd += __shfl_xor_sync(0xffffffffu, pd, 4);

        const float wa = exp2f(pa * C);
        const float wb = exp2f(pb * C);
        const float wc = exp2f(pc * C);
        const float wd = exp2f(pd * C);
        sA += wa + wc;
        sB += wb + wd;

        accA.x = fmaf(wa, a.x, accA.x);  accB.x = fmaf(wb, b.x, accB.x);
        accA.y = fmaf(wa, a.y, accA.y);  accB.y = fmaf(wb, b.y, accB.y);
        accA.z = fmaf(wa, a.z, accA.z);  accB.z = fmaf(wb, b.z, accB.z);
        accA.w = fmaf(wa, a.w, accA.w);  accB.w = fmaf(wb, b.w, accB.w);
        accA.x = fmaf(wc, c.x, accA.x);  accB.x = fmaf(wd, d.x, accB.x);
        accA.y = fmaf(wc, c.y, accA.y);  accB.y = fmaf(wd, d.y, accB.y);
        accA.z = fmaf(wc, c.z, accA.z);  accB.z = fmaf(wd, d.z, accB.z);
        accA.w = fmaf(wc, c.w, accA.w);  accB.w = fmaf(wd, d.w, accB.w);
    }
    // tail
    for (; i < end; i++) EDGE_ONE(__ldg(&src[i]));
#undef EDGE_ONE

    const float inv = 1.f / (sA + sB);
    *outp = make_float4((accA.x + accB.x) * inv,
                        (accA.y + accB.y) * inv,
                        (accA.z + accB.z) * inv,
                        (accA.w + accB.w) * inv);
}

// ---------------------------------------------------------------------------
// Launch
// ---------------------------------------------------------------------------
extern "C" void kernel_launch(void* const* d_in, const int* in_sizes, int n_in,
                              void* d_out, int out_size)
{
    const float* feat = (const float*)d_in[0];
    const int*   src  = (const int*)d_in[1];
    const int*   dst  = (const int*)d_in[2];
    const float* W    = (const float*)d_in[3];
    float*       out  = (float*)d_out;

    const int N = in_sizes[0] / IN_SIZE;   // 50000
    const int E = in_sizes[1];             // 1600000

    static bool attr_done = false;
    if (!attr_done) {
        cudaFuncSetAttribute(proj_gemm_kernel,
                             cudaFuncAttributeMaxDynamicSharedMemorySize,
                             GEMM_SMEM);
        attr_done = true;
    }

    rowptr_scatter4_kernel<<<(E / 4 + 255) / 256, 256>>>(dst, E, N);
    proj_gemm_kernel<<<(N + 127) / 128, 256, GEMM_SMEM>>>(feat, W, N);
    edge_warp_kernel<<<(N + WPB - 1) / WPB, WPB * 32>>>(src, out, N);
}